// round 1
// baseline (speedup 1.0000x reference)
#include <cuda_runtime.h>

#define NN 100000
#define EE 1600000
#define ET (EE + NN)
#define BB 1024

// ---------------- scratch (device globals; no allocation allowed) ------------
__device__ __align__(128) float d_h   [NN * 128];  // GAT transformed features
__device__ __align__(128) float d_as  [NN * 4];
__device__ __align__(128) float d_ad  [NN * 4];
__device__ __align__(128) float d_m   [NN * 4];    // segment max
__device__ __align__(128) float d_s   [NN * 4];    // segment sum of exp
__device__ __align__(128) float d_gat [NN * 128];  // GAT output (init = bias)
__device__ __align__(128) float d_h1  [NN * 64];   // leaky(gat) @ W2
__device__ __align__(128) float d_o2  [NN * 64];   // GCN1 out (init = b2)
__device__ __align__(128) float d_h2  [NN * 128];  // leaky(o2) @ W3
__device__ __align__(128) float d_o3  [NN * 128];  // GCN2 out (init = b3)
__device__ __align__(128) float d_deg [NN];
__device__ __align__(128) float d_dinv[NN];
__device__ __align__(128) float d_pool[BB * 128];
__device__ __align__(128) float d_cnt [BB];
__device__ __align__(128) float d_s1  [BB * 64 * 18];
__device__ __align__(128) float d_s2  [BB * 64 * 16];
__device__ __align__(128) float d_fc  [BB * 64];

// ---------------- helpers ----------------------------------------------------
__device__ __forceinline__ float lrelu(float x, float s) { return x < 0.f ? s * x : x; }

__device__ __forceinline__ void atomicMaxF(float* addr, float v) {
    if (v >= 0.f) atomicMax((int*)addr, __float_as_int(v));
    else          atomicMin((unsigned int*)addr, __float_as_uint(v));
}

// sm_90+ vector reduction (no return) — 4 floats per L2 atomic op
__device__ __forceinline__ void redAdd4(float* p, float a, float b, float c, float d) {
    asm volatile("red.global.add.v4.f32 [%0], {%1,%2,%3,%4};"
                 :: "l"(p), "f"(a), "f"(b), "f"(c), "f"(d) : "memory");
}

// ---------------- init -------------------------------------------------------
__global__ void k_init(const float* __restrict__ bg, const float* __restrict__ b2,
                       const float* __restrict__ b3) {
    int idx = blockIdx.x * 256 + threadIdx.x;           // exactly NN*128 threads
    d_gat[idx] = bg[idx & 127];
    d_o3[idx]  = b3[idx & 127];
    if (idx < NN * 64) d_o2[idx] = b2[idx & 63];
    if (idx < NN * 4) { d_m[idx] = __int_as_float(0xff800000); d_s[idx] = 0.f; }
    if (idx < NN)      d_deg[idx] = 1.0f;               // self loop
    if (idx < BB * 128) d_pool[idx] = 0.f;
    if (idx < BB)      d_cnt[idx] = 0.f;
}

// ---------------- node transform: h = x @ W_gat, attention logits ------------
__global__ void k_node(const float* __restrict__ x, const float* __restrict__ Wg,
                       const float* __restrict__ atts, const float* __restrict__ attd) {
    int idx = blockIdx.x * 256 + threadIdx.x;           // NN*128 threads
    int node = idx >> 7, f = idx & 127;
    float acc = 0.f;
    #pragma unroll
    for (int k = 0; k < 9; k++) acc += x[node * 9 + k] * Wg[k * 128 + f];
    d_h[idx] = acc;
    int head = f >> 5, c = f & 31;
    float ts = acc * atts[head * 32 + c];
    float td = acc * attd[head * 32 + c];
    #pragma unroll
    for (int off = 16; off > 0; off >>= 1) {
        ts += __shfl_xor_sync(0xffffffffu, ts, off);
        td += __shfl_xor_sync(0xffffffffu, td, off);
    }
    if ((threadIdx.x & 31) == 0) {
        d_as[node * 4 + head] = ts;
        d_ad[node * 4 + head] = td;
    }
}

// ---------------- degree + batch counts --------------------------------------
__global__ void k_degcnt(const int* __restrict__ ei, const int* __restrict__ batch) {
    int idx = blockIdx.x * 256 + threadIdx.x;
    if (idx < EE) atomicAdd(&d_deg[ei[EE + idx]], 1.0f);
    if (idx < NN) atomicAdd(&d_cnt[batch[idx]], 1.0f);
}

__global__ void k_dinv() {
    int i = blockIdx.x * 256 + threadIdx.x;
    if (i < NN) d_dinv[i] = rsqrtf(d_deg[i]);
}

// ---------------- GAT pass A: segment max of attention logits ----------------
__global__ void k_passA(const int* __restrict__ ei) {
    int idx = blockIdx.x * 256 + threadIdx.x;
    if (idx >= ET) return;
    int s, d;
    if (idx < EE) { s = ei[idx]; d = ei[EE + idx]; } else { s = d = idx - EE; }
    float4 as = *(const float4*)&d_as[s * 4];
    float4 ad = *(const float4*)&d_ad[d * 4];
    float e0 = lrelu(as.x + ad.x, 0.2f), e1 = lrelu(as.y + ad.y, 0.2f);
    float e2 = lrelu(as.z + ad.z, 0.2f), e3 = lrelu(as.w + ad.w, 0.2f);
    atomicMaxF(&d_m[d * 4 + 0], e0);
    atomicMaxF(&d_m[d * 4 + 1], e1);
    atomicMaxF(&d_m[d * 4 + 2], e2);
    atomicMaxF(&d_m[d * 4 + 3], e3);
}

// ---------------- GAT pass B: segment sum of exp ------------------------------
__global__ void k_passB(const int* __restrict__ ei) {
    int idx = blockIdx.x * 256 + threadIdx.x;
    if (idx >= ET) return;
    int s, d;
    if (idx < EE) { s = ei[idx]; d = ei[EE + idx]; } else { s = d = idx - EE; }
    float4 as = *(const float4*)&d_as[s * 4];
    float4 ad = *(const float4*)&d_ad[d * 4];
    float4 mm = *(const float4*)&d_m[d * 4];
    redAdd4(&d_s[d * 4],
            __expf(lrelu(as.x + ad.x, 0.2f) - mm.x),
            __expf(lrelu(as.y + ad.y, 0.2f) - mm.y),
            __expf(lrelu(as.z + ad.z, 0.2f) - mm.z),
            __expf(lrelu(as.w + ad.w, 0.2f) - mm.w));
}

// ---------------- GAT pass C: weighted message scatter (warp/edge) -----------
__global__ void k_passC(const int* __restrict__ ei) {
    int gw = (blockIdx.x * 256 + threadIdx.x) >> 5;
    if (gw >= ET) return;
    int lane = threadIdx.x & 31;
    int s, d;
    if (gw < EE) { s = ei[gw]; d = ei[EE + gw]; } else { s = d = gw - EE; }
    int hd = lane >> 3;  // 8 lanes per head (4 floats each = 32 feats/head)
    float as = d_as[s * 4 + hd], ad = d_ad[d * 4 + hd];
    float mm = d_m[d * 4 + hd],  ss = d_s[d * 4 + hd];
    float e = lrelu(as + ad, 0.2f);
    float alpha = __expf(e - mm) / (ss + 1e-16f);
    float4 hv = *(const float4*)&d_h[s * 128 + lane * 4];
    redAdd4(&d_gat[d * 128 + lane * 4],
            hv.x * alpha, hv.y * alpha, hv.z * alpha, hv.w * alpha);
}

// ---------------- GEMM1: h1 = leaky(gat) @ W2  (128 -> 64) -------------------
__global__ void k_gemm1(const float* __restrict__ W2) {
    __shared__ float Ws[128 * 64];
    for (int i = threadIdx.x; i < 128 * 64; i += 256) Ws[i] = W2[i];
    __syncthreads();
    int o = threadIdx.x & 63, nl = threadIdx.x >> 6;
    for (int n0 = blockIdx.x * 4; n0 < NN; n0 += gridDim.x * 4) {
        int node = n0 + nl;
        if (node < NN) {
            const float* g = &d_gat[node * 128];
            float acc = 0.f;
            #pragma unroll 8
            for (int k = 0; k < 128; k++) {
                float gv = g[k];
                gv = gv < 0.f ? 0.01f * gv : gv;
                acc += gv * Ws[k * 64 + o];
            }
            d_h1[node * 64 + o] = acc;
        }
    }
}

// ---------------- GCN1 scatter: o2 += h1[src] * norm -------------------------
__global__ void k_gcn1(const int* __restrict__ ei) {
    int idx = blockIdx.x * 256 + threadIdx.x;       // ET*16 threads
    int e = idx >> 4, q = idx & 15;
    if (e >= ET) return;
    int s, d;
    if (e < EE) { s = ei[e]; d = ei[EE + e]; } else { s = d = e - EE; }
    float norm = d_dinv[s] * d_dinv[d];
    float4 v = *(const float4*)&d_h1[s * 64 + q * 4];
    redAdd4(&d_o2[d * 64 + q * 4], v.x * norm, v.y * norm, v.z * norm, v.w * norm);
}

// ---------------- GEMM2: h2 = leaky(o2) @ W3  (64 -> 128) --------------------
__global__ void k_gemm2(const float* __restrict__ W3) {
    __shared__ float Ws[64 * 128];
    for (int i = threadIdx.x; i < 64 * 128; i += 256) Ws[i] = W3[i];
    __syncthreads();
    int o = threadIdx.x & 127, nl = threadIdx.x >> 7;
    for (int n0 = blockIdx.x * 2; n0 < NN; n0 += gridDim.x * 2) {
        int node = n0 + nl;
        if (node < NN) {
            const float* g = &d_o2[node * 64];
            float acc = 0.f;
            #pragma unroll 8
            for (int k = 0; k < 64; k++) {
                float gv = g[k];
                gv = gv < 0.f ? 0.01f * gv : gv;
                acc += gv * Ws[k * 128 + o];
            }
            d_h2[node * 128 + o] = acc;
        }
    }
}

// ---------------- GCN2 scatter (warp/edge) -----------------------------------
__global__ void k_gcn2(const int* __restrict__ ei) {
    int gw = (blockIdx.x * 256 + threadIdx.x) >> 5;
    if (gw >= ET) return;
    int lane = threadIdx.x & 31;
    int s, d;
    if (gw < EE) { s = ei[gw]; d = ei[EE + gw]; } else { s = d = gw - EE; }
    float norm = d_dinv[s] * d_dinv[d];
    float4 v = *(const float4*)&d_h2[s * 128 + lane * 4];
    redAdd4(&d_o3[d * 128 + lane * 4], v.x * norm, v.y * norm, v.z * norm, v.w * norm);
}

// ---------------- pool: sum leaky(o3) per graph ------------------------------
__global__ void k_pool(const int* __restrict__ batch) {
    int idx = blockIdx.x * 256 + threadIdx.x;       // NN*32 threads
    int node = idx >> 5, q = idx & 31;
    float4 v = *(const float4*)&d_o3[node * 128 + q * 4];
    int b = batch[node];
    redAdd4(&d_pool[b * 128 + q * 4],
            lrelu(v.x, 0.01f), lrelu(v.y, 0.01f), lrelu(v.z, 0.01f), lrelu(v.w, 0.01f));
}

// ---------------- sequence branch --------------------------------------------
__global__ void k_seq1(const float* __restrict__ seq, const float* __restrict__ w,
                       const float* __restrict__ bias,
                       const float* __restrict__ g, const float* __restrict__ be,
                       const float* __restrict__ m, const float* __restrict__ v) {
    int idx = blockIdx.x * 256 + threadIdx.x;       // BB*64*18
    int b = idx / 1152, r = idx % 1152, co = r / 18, t = r % 18;
    float acc = bias[co];
    #pragma unroll 5
    for (int ci = 0; ci < 30; ci++) {
        const float* sp = &seq[b * 600 + ci * 20 + t];
        const float* wp = &w[(co * 30 + ci) * 3];
        acc += sp[0] * wp[0] + sp[1] * wp[1] + sp[2] * wp[2];
    }
    acc = (acc - m[co]) * rsqrtf(v[co] + 1e-5f) * g[co] + be[co];
    d_s1[idx] = lrelu(acc, 0.01f);
}

__global__ void k_seq2(const float* __restrict__ w, const float* __restrict__ bias,
                       const float* __restrict__ g, const float* __restrict__ be,
                       const float* __restrict__ m, const float* __restrict__ v) {
    int idx = blockIdx.x * 256 + threadIdx.x;       // BB*64*16
    int b = idx >> 10, r = idx & 1023, co = r >> 4, t = r & 15;
    float acc = bias[co];
    #pragma unroll 8
    for (int ci = 0; ci < 64; ci++) {
        const float* sp = &d_s1[b * 1152 + ci * 18 + t];
        const float* wp = &w[(co * 64 + ci) * 3];
        acc += sp[0] * wp[0] + sp[1] * wp[1] + sp[2] * wp[2];
    }
    acc = (acc - m[co]) * rsqrtf(v[co] + 1e-5f) * g[co] + be[co];
    d_s2[idx] = lrelu(acc, 0.01f);
}

__global__ void k_fc1(const float* __restrict__ W, const float* __restrict__ bias) {
    int idx = blockIdx.x * 256 + threadIdx.x;       // BB*64
    int b = idx >> 6, o = idx & 63;
    float acc = bias[o];
    const float* sp = &d_s2[b * 1024];
    #pragma unroll 8
    for (int k = 0; k < 1024; k++) acc += sp[k] * W[k * 64 + o];
    d_fc[idx] = acc;
}

// ---------------- fusion + classifier head -----------------------------------
__global__ void k_head(const float* __restrict__ fusW, const float* __restrict__ fusb,
                       const float* __restrict__ c1W, const float* __restrict__ c1b,
                       const float* __restrict__ c3W, const float* __restrict__ c3b,
                       float* __restrict__ out) {
    __shared__ float comb[192], t1[128], t2[64];
    int b = blockIdx.x, tid = threadIdx.x;          // 128 threads
    if (tid < 128) comb[tid] = d_pool[b * 128 + tid] / fmaxf(d_cnt[b], 1.0f);
    if (tid < 64)  comb[128 + tid] = d_fc[b * 64 + tid];
    __syncthreads();
    float acc = fusb[tid];
    #pragma unroll 8
    for (int k = 0; k < 192; k++) acc += comb[k] * fusW[k * 128 + tid];
    t1[tid] = lrelu(acc, 0.01f);
    __syncthreads();
    if (tid < 64) {
        float a = c1b[tid];
        #pragma unroll 8
        for (int k = 0; k < 128; k++) a += t1[k] * c1W[k * 64 + tid];
        t2[tid] = lrelu(a, 0.01f);
    }
    __syncthreads();
    if (tid == 0) {
        float a = c3b[0];
        #pragma unroll 8
        for (int k = 0; k < 64; k++) a += t2[k] * c3W[k];
        out[b] = a;
    }
}

// ---------------- launch ------------------------------------------------------
extern "C" void kernel_launch(void* const* d_in, const int* in_sizes, int n_in,
                              void* d_out, int out_size) {
    const float* x     = (const float*)d_in[0];
    const int*   ei    = (const int*)  d_in[1];
    const int*   batch = (const int*)  d_in[2];
    const float* seq   = (const float*)d_in[3];
    const float* Wg    = (const float*)d_in[4];
    const float* atts  = (const float*)d_in[5];
    const float* attd  = (const float*)d_in[6];
    const float* bg    = (const float*)d_in[7];
    const float* W2    = (const float*)d_in[8];
    const float* b2    = (const float*)d_in[9];
    const float* W3    = (const float*)d_in[10];
    const float* b3    = (const float*)d_in[11];
    const float* c1w   = (const float*)d_in[12];
    const float* c1bv  = (const float*)d_in[13];
    const float* c2w   = (const float*)d_in[14];
    const float* c2bv  = (const float*)d_in[15];
    const float* bn1g  = (const float*)d_in[16];
    const float* bn1b  = (const float*)d_in[17];
    const float* bn1m  = (const float*)d_in[18];
    const float* bn1v  = (const float*)d_in[19];
    const float* bn2g  = (const float*)d_in[20];
    const float* bn2b  = (const float*)d_in[21];
    const float* bn2m  = (const float*)d_in[22];
    const float* bn2v  = (const float*)d_in[23];
    const float* fcW   = (const float*)d_in[24];
    const float* fcb   = (const float*)d_in[25];
    const float* fusW  = (const float*)d_in[26];
    const float* fusb  = (const float*)d_in[27];
    const float* cls1W = (const float*)d_in[28];
    const float* cls1b = (const float*)d_in[29];
    const float* cls3W = (const float*)d_in[30];
    const float* cls3b = (const float*)d_in[31];
    float* out = (float*)d_out;

    k_init  <<<50000, 256>>>(bg, b2, b3);                      // NN*128
    k_node  <<<50000, 256>>>(x, Wg, atts, attd);               // NN*128
    k_degcnt<<<(EE + 255) / 256, 256>>>(ei, batch);
    k_dinv  <<<(NN + 255) / 256, 256>>>();
    k_passA <<<(ET + 255) / 256, 256>>>(ei);
    k_passB <<<(ET + 255) / 256, 256>>>(ei);
    k_passC <<<ET / 8, 256>>>(ei);                             // warp per edge
    k_gemm1 <<<1184, 256>>>(W2);
    k_gcn1  <<<ET * 16 / 256, 256>>>(ei);
    k_gemm2 <<<1184, 256>>>(W3);
    k_gcn2  <<<ET / 8, 256>>>(ei);
    k_pool  <<<NN * 32 / 256, 256>>>(batch);
    k_seq1  <<<BB * 1152 / 256, 256>>>(seq, c1w, c1bv, bn1g, bn1b, bn1m, bn1v);
    k_seq2  <<<BB * 1024 / 256, 256>>>(c2w, c2bv, bn2g, bn2b, bn2m, bn2v);
    k_fc1   <<<BB * 64 / 256, 256>>>(fcW, fcb);
    k_head  <<<BB, 128>>>(fusW, fusb, cls1W, cls1b, cls3W, cls3b, out);
}

// round 2
// speedup vs baseline: 1.4275x; 1.4275x over previous
#include <cuda_runtime.h>

#define NN 100000
#define EE 1600000
#define BB 1024
#define SCAN_B 98   // ceil(NN/1024)

// ---------------- scratch (device globals) -----------------------------------
__device__ __align__(128) float d_h   [NN * 128];  // GAT transformed features (pre-attn)
__device__ __align__(128) float d_as  [NN * 4];
__device__ __align__(128) float d_ad  [NN * 4];
__device__ __align__(128) float d_gat [NN * 128];  // post-leaky GAT output
__device__ __align__(128) float d_h1  [NN * 64];   // d_gat @ W2
__device__ __align__(128) float d_o2  [NN * 64];   // post-leaky GCN1 output
__device__ __align__(128) float d_h2  [NN * 128];  // d_o2 @ W3
__device__ __align__(128) float d_dinv[NN];
__device__ __align__(128) float d_pool[BB * 128];
__device__ __align__(128) float d_cnt [BB];
__device__ __align__(128) float d_s1  [BB * 64 * 18];
__device__ __align__(128) float d_s2  [BB * 64 * 16];
__device__ __align__(128) float d_fc  [BB * 64];
__device__ __align__(128) int   d_degi[NN];        // in-degree (excl self loop)
__device__ __align__(128) int   d_off [NN];        // CSR row start
__device__ __align__(128) int   d_cur [NN];        // fill cursor
__device__ __align__(128) int   d_csr [EE];        // src list grouped by dst
__device__ __align__(128) int   d_bsum [SCAN_B];
__device__ __align__(128) int   d_bbase[SCAN_B];

__device__ __forceinline__ float lrelu(float x, float s) { return x < 0.f ? s * x : x; }

__device__ __forceinline__ void redAdd4(float* p, float a, float b, float c, float d) {
    asm volatile("red.global.add.v4.f32 [%0], {%1,%2,%3,%4};"
                 :: "l"(p), "f"(a), "f"(b), "f"(c), "f"(d) : "memory");
}

// ---------------- init --------------------------------------------------------
__global__ void k_init() {
    int i = blockIdx.x * 256 + threadIdx.x;        // covers BB*128 = 131072
    if (i < NN)       d_degi[i] = 0;
    if (i < BB * 128) d_pool[i] = 0.f;
    if (i < BB)       d_cnt[i]  = 0.f;
}

// ---------------- node transform: h = x @ W_gat, attention logits -------------
__global__ void k_node(const float* __restrict__ x, const float* __restrict__ Wg,
                       const float* __restrict__ atts, const float* __restrict__ attd) {
    int idx = blockIdx.x * 256 + threadIdx.x;      // NN*128 threads
    int node = idx >> 7, f = idx & 127;
    float acc = 0.f;
    #pragma unroll
    for (int k = 0; k < 9; k++) acc += x[node * 9 + k] * Wg[k * 128 + f];
    d_h[idx] = acc;
    int head = f >> 5, c = f & 31;
    float ts = acc * atts[head * 32 + c];
    float td = acc * attd[head * 32 + c];
    #pragma unroll
    for (int off = 16; off > 0; off >>= 1) {
        ts += __shfl_xor_sync(0xffffffffu, ts, off);
        td += __shfl_xor_sync(0xffffffffu, td, off);
    }
    if ((threadIdx.x & 31) == 0) {
        d_as[node * 4 + head] = ts;
        d_ad[node * 4 + head] = td;
    }
}

// ---------------- degree histogram + batch counts -----------------------------
__global__ void k_hist(const int* __restrict__ ei, const int* __restrict__ batch) {
    int idx = blockIdx.x * 256 + threadIdx.x;
    if (idx < EE) atomicAdd(&d_degi[ei[EE + idx]], 1);
    if (idx < NN) atomicAdd(&d_cnt[batch[idx]], 1.0f);
}

// ---------------- 3-step exclusive scan of d_degi -> d_off --------------------
__global__ void k_scanA() {
    __shared__ int sm[1024];
    int i = blockIdx.x * 1024 + threadIdx.x;
    int v = (i < NN) ? d_degi[i] : 0;
    sm[threadIdx.x] = v;
    __syncthreads();
    for (int off = 1; off < 1024; off <<= 1) {
        int t = (threadIdx.x >= off) ? sm[threadIdx.x - off] : 0;
        __syncthreads();
        sm[threadIdx.x] += t;
        __syncthreads();
    }
    if (i < NN) d_off[i] = sm[threadIdx.x] - v;   // exclusive within block
    if (threadIdx.x == 1023) d_bsum[blockIdx.x] = sm[1023];
}

__global__ void k_scanB() {
    if (threadIdx.x == 0) {
        int run = 0;
        for (int b = 0; b < SCAN_B; b++) { d_bbase[b] = run; run += d_bsum[b]; }
    }
}

__global__ void k_scanC() {
    int i = blockIdx.x * 1024 + threadIdx.x;
    if (i < NN) {
        int o = d_off[i] + d_bbase[blockIdx.x];
        d_off[i] = o;
        d_cur[i] = o;
        d_dinv[i] = rsqrtf((float)(d_degi[i] + 1));  // +1 self loop
    }
}

// ---------------- CSR fill ----------------------------------------------------
__global__ void k_fill(const int* __restrict__ ei) {
    int idx = blockIdx.x * 256 + threadIdx.x;
    if (idx < EE) {
        int dst = ei[EE + idx];
        int p = atomicAdd(&d_cur[dst], 1);
        d_csr[p] = ei[idx];
    }
}

// ---------------- fused GAT: online-softmax gather (warp per dst node) --------
__global__ void k_gat(const float* __restrict__ bg) {
    int gw = (blockIdx.x * 256 + threadIdx.x) >> 5;   // node id
    if (gw >= NN) return;
    int lane = threadIdx.x & 31;
    int h = lane >> 3;                                 // head (4 heads x 8 lanes)
    int d = gw;

    float add_ = d_ad[d * 4 + h];
    // self loop seeds the online softmax
    float m = lrelu(d_as[d * 4 + h] + add_, 0.2f);
    float s = 1.0f;
    float4 acc = *(const float4*)&d_h[d * 128 + lane * 4];

    int start = d_off[d];
    int cntE  = d_degi[d];
    for (int p0 = 0; p0 < cntE; p0 += 32) {
        int src_l = (p0 + lane < cntE) ? d_csr[start + p0 + lane] : 0;
        int lim = min(32, cntE - p0);
        for (int j = 0; j < lim; j++) {
            int src = __shfl_sync(0xffffffffu, src_l, j);
            float e = lrelu(d_as[src * 4 + h] + add_, 0.2f);
            float4 hv = *(const float4*)&d_h[src * 128 + lane * 4];
            if (e <= m) {
                float w = __expf(e - m);
                s += w;
                acc.x += hv.x * w; acc.y += hv.y * w;
                acc.z += hv.z * w; acc.w += hv.w * w;
            } else {
                float r = __expf(m - e);
                s = s * r + 1.0f;
                acc.x = acc.x * r + hv.x; acc.y = acc.y * r + hv.y;
                acc.z = acc.z * r + hv.z; acc.w = acc.w * r + hv.w;
                m = e;
            }
        }
    }
    float inv = 1.0f / (s + 1e-16f);
    float4 bb = *(const float4*)&bg[lane * 4];
    float4 o;
    o.x = lrelu(acc.x * inv + bb.x, 0.01f);
    o.y = lrelu(acc.y * inv + bb.y, 0.01f);
    o.z = lrelu(acc.z * inv + bb.z, 0.01f);
    o.w = lrelu(acc.w * inv + bb.w, 0.01f);
    *(float4*)&d_gat[d * 128 + lane * 4] = o;
}

// ---------------- GEMM1: h1 = d_gat @ W2 (128 -> 64) --------------------------
__global__ void k_gemm1(const float* __restrict__ W2) {
    __shared__ float Ws[128 * 64];
    for (int i = threadIdx.x; i < 128 * 64; i += 256) Ws[i] = W2[i];
    __syncthreads();
    int o = threadIdx.x & 63, nl = threadIdx.x >> 6;
    for (int n0 = blockIdx.x * 4; n0 < NN; n0 += gridDim.x * 4) {
        int node = n0 + nl;
        if (node < NN) {
            const float* g = &d_gat[node * 128];
            float acc = 0.f;
            #pragma unroll 8
            for (int k = 0; k < 128; k++) acc += g[k] * Ws[k * 64 + o];
            d_h1[node * 64 + o] = acc;
        }
    }
}

// ---------------- GCN1 gather (warp per node, 64 feats = float2/lane) ---------
__global__ void k_gcn1(const float* __restrict__ b2) {
    int gw = (blockIdx.x * 256 + threadIdx.x) >> 5;
    if (gw >= NN) return;
    int lane = threadIdx.x & 31;
    int d = gw;
    float did = d_dinv[d];

    float2 hv = *(const float2*)&d_h1[d * 64 + lane * 2];
    float2 acc; acc.x = hv.x * did; acc.y = hv.y * did;  // self term

    int start = d_off[d];
    int cntE  = d_degi[d];
    for (int p0 = 0; p0 < cntE; p0 += 32) {
        int   src_l = 0;
        float dv_l  = 0.f;
        if (p0 + lane < cntE) { src_l = d_csr[start + p0 + lane]; dv_l = d_dinv[src_l]; }
        int lim = min(32, cntE - p0);
        for (int j = 0; j < lim; j++) {
            int   src = __shfl_sync(0xffffffffu, src_l, j);
            float dv  = __shfl_sync(0xffffffffu, dv_l, j);
            float2 v = *(const float2*)&d_h1[src * 64 + lane * 2];
            acc.x += v.x * dv; acc.y += v.y * dv;
        }
    }
    float2 o;
    o.x = lrelu(acc.x * did + b2[lane * 2 + 0], 0.01f);
    o.y = lrelu(acc.y * did + b2[lane * 2 + 1], 0.01f);
    *(float2*)&d_o2[d * 64 + lane * 2] = o;
}

// ---------------- GEMM2: h2 = d_o2 @ W3 (64 -> 128) ---------------------------
__global__ void k_gemm2(const float* __restrict__ W3) {
    __shared__ float Ws[64 * 128];
    for (int i = threadIdx.x; i < 64 * 128; i += 256) Ws[i] = W3[i];
    __syncthreads();
    int o = threadIdx.x & 127, nl = threadIdx.x >> 7;
    for (int n0 = blockIdx.x * 2; n0 < NN; n0 += gridDim.x * 2) {
        int node = n0 + nl;
        if (node < NN) {
            const float* g = &d_o2[node * 64];
            float acc = 0.f;
            #pragma unroll 8
            for (int k = 0; k < 64; k++) acc += g[k] * Ws[k * 128 + o];
            d_h2[node * 128 + o] = acc;
        }
    }
}

// ---------------- GCN2 gather + fused pool (warp per node) --------------------
__global__ void k_gcn2pool(const float* __restrict__ b3, const int* __restrict__ batch) {
    int gw = (blockIdx.x * 256 + threadIdx.x) >> 5;
    if (gw >= NN) return;
    int lane = threadIdx.x & 31;
    int d = gw;
    float did = d_dinv[d];

    float4 hv = *(const float4*)&d_h2[d * 128 + lane * 4];
    float4 acc; acc.x = hv.x * did; acc.y = hv.y * did; acc.z = hv.z * did; acc.w = hv.w * did;

    int start = d_off[d];
    int cntE  = d_degi[d];
    for (int p0 = 0; p0 < cntE; p0 += 32) {
        int   src_l = 0;
        float dv_l  = 0.f;
        if (p0 + lane < cntE) { src_l = d_csr[start + p0 + lane]; dv_l = d_dinv[src_l]; }
        int lim = min(32, cntE - p0);
        for (int j = 0; j < lim; j++) {
            int   src = __shfl_sync(0xffffffffu, src_l, j);
            float dv  = __shfl_sync(0xffffffffu, dv_l, j);
            float4 v = *(const float4*)&d_h2[src * 128 + lane * 4];
            acc.x += v.x * dv; acc.y += v.y * dv; acc.z += v.z * dv; acc.w += v.w * dv;
        }
    }
    float4 bb = *(const float4*)&b3[lane * 4];
    float ox = lrelu(acc.x * did + bb.x, 0.01f);
    float oy = lrelu(acc.y * did + bb.y, 0.01f);
    float oz = lrelu(acc.z * did + bb.z, 0.01f);
    float ow = lrelu(acc.w * did + bb.w, 0.01f);
    int b = batch[d];
    redAdd4(&d_pool[b * 128 + lane * 4], ox, oy, oz, ow);
}

// ---------------- sequence branch ---------------------------------------------
__global__ void k_seq1(const float* __restrict__ seq, const float* __restrict__ w,
                       const float* __restrict__ bias,
                       const float* __restrict__ g, const float* __restrict__ be,
                       const float* __restrict__ m, const float* __restrict__ v) {
    int idx = blockIdx.x * 256 + threadIdx.x;       // BB*64*18
    int b = idx / 1152, r = idx % 1152, co = r / 18, t = r % 18;
    float acc = bias[co];
    #pragma unroll 5
    for (int ci = 0; ci < 30; ci++) {
        const float* sp = &seq[b * 600 + ci * 20 + t];
        const float* wp = &w[(co * 30 + ci) * 3];
        acc += sp[0] * wp[0] + sp[1] * wp[1] + sp[2] * wp[2];
    }
    acc = (acc - m[co]) * rsqrtf(v[co] + 1e-5f) * g[co] + be[co];
    d_s1[idx] = lrelu(acc, 0.01f);
}

__global__ void k_seq2(const float* __restrict__ w, const float* __restrict__ bias,
                       const float* __restrict__ g, const float* __restrict__ be,
                       const float* __restrict__ m, const float* __restrict__ v) {
    int idx = blockIdx.x * 256 + threadIdx.x;       // BB*64*16
    int b = idx >> 10, r = idx & 1023, co = r >> 4, t = r & 15;
    float acc = bias[co];
    #pragma unroll 8
    for (int ci = 0; ci < 64; ci++) {
        const float* sp = &d_s1[b * 1152 + ci * 18 + t];
        const float* wp = &w[(co * 64 + ci) * 3];
        acc += sp[0] * wp[0] + sp[1] * wp[1] + sp[2] * wp[2];
    }
    acc = (acc - m[co]) * rsqrtf(v[co] + 1e-5f) * g[co] + be[co];
    d_s2[idx] = lrelu(acc, 0.01f);
}

__global__ void k_fc1(const float* __restrict__ W, const float* __restrict__ bias) {
    int idx = blockIdx.x * 256 + threadIdx.x;       // BB*64
    int b = idx >> 6, o = idx & 63;
    float acc = bias[o];
    const float* sp = &d_s2[b * 1024];
    #pragma unroll 8
    for (int k = 0; k < 1024; k++) acc += sp[k] * W[k * 64 + o];
    d_fc[idx] = acc;
}

// ---------------- fusion + classifier head ------------------------------------
__global__ void k_head(const float* __restrict__ fusW, const float* __restrict__ fusb,
                       const float* __restrict__ c1W, const float* __restrict__ c1b,
                       const float* __restrict__ c3W, const float* __restrict__ c3b,
                       float* __restrict__ out) {
    __shared__ float comb[192], t1[128], t2[64];
    int b = blockIdx.x, tid = threadIdx.x;          // 128 threads
    if (tid < 128) comb[tid] = d_pool[b * 128 + tid] / fmaxf(d_cnt[b], 1.0f);
    if (tid < 64)  comb[128 + tid] = d_fc[b * 64 + tid];
    __syncthreads();
    float acc = fusb[tid];
    #pragma unroll 8
    for (int k = 0; k < 192; k++) acc += comb[k] * fusW[k * 128 + tid];
    t1[tid] = lrelu(acc, 0.01f);
    __syncthreads();
    if (tid < 64) {
        float a = c1b[tid];
        #pragma unroll 8
        for (int k = 0; k < 128; k++) a += t1[k] * c1W[k * 64 + tid];
        t2[tid] = lrelu(a, 0.01f);
    }
    __syncthreads();
    if (tid == 0) {
        float a = c3b[0];
        #pragma unroll 8
        for (int k = 0; k < 64; k++) a += t2[k] * c3W[k];
        out[b] = a;
    }
}

// ---------------- launch ------------------------------------------------------
extern "C" void kernel_launch(void* const* d_in, const int* in_sizes, int n_in,
                              void* d_out, int out_size) {
    const float* x     = (const float*)d_in[0];
    const int*   ei    = (const int*)  d_in[1];
    const int*   batch = (const int*)  d_in[2];
    const float* seq   = (const float*)d_in[3];
    const float* Wg    = (const float*)d_in[4];
    const float* atts  = (const float*)d_in[5];
    const float* attd  = (const float*)d_in[6];
    const float* bg    = (const float*)d_in[7];
    const float* W2    = (const float*)d_in[8];
    const float* b2    = (const float*)d_in[9];
    const float* W3    = (const float*)d_in[10];
    const float* b3    = (const float*)d_in[11];
    const float* c1w   = (const float*)d_in[12];
    const float* c1bv  = (const float*)d_in[13];
    const float* c2w   = (const float*)d_in[14];
    const float* c2bv  = (const float*)d_in[15];
    const float* bn1g  = (const float*)d_in[16];
    const float* bn1b  = (const float*)d_in[17];
    const float* bn1m  = (const float*)d_in[18];
    const float* bn1v  = (const float*)d_in[19];
    const float* bn2g  = (const float*)d_in[20];
    const float* bn2b  = (const float*)d_in[21];
    const float* bn2m  = (const float*)d_in[22];
    const float* bn2v  = (const float*)d_in[23];
    const float* fcW   = (const float*)d_in[24];
    const float* fcb   = (const float*)d_in[25];
    const float* fusW  = (const float*)d_in[26];
    const float* fusb  = (const float*)d_in[27];
    const float* cls1W = (const float*)d_in[28];
    const float* cls1b = (const float*)d_in[29];
    const float* cls3W = (const float*)d_in[30];
    const float* cls3b = (const float*)d_in[31];
    float* out = (float*)d_out;

    k_init  <<<512, 256>>>();                                  // BB*128 cover
    k_node  <<<50000, 256>>>(x, Wg, atts, attd);               // NN*128 threads
    k_hist  <<<(EE + 255) / 256, 256>>>(ei, batch);
    k_scanA <<<SCAN_B, 1024>>>();
    k_scanB <<<1, 32>>>();
    k_scanC <<<SCAN_B, 1024>>>();
    k_fill  <<<(EE + 255) / 256, 256>>>(ei);
    k_gat   <<<12500, 256>>>(bg);                              // warp per node
    k_gemm1 <<<1184, 256>>>(W2);
    k_gcn1  <<<12500, 256>>>(b2);
    k_gemm2 <<<1184, 256>>>(W3);
    k_gcn2pool<<<12500, 256>>>(b3, batch);
    k_seq1  <<<BB * 1152 / 256, 256>>>(seq, c1w, c1bv, bn1g, bn1b, bn1m, bn1v);
    k_seq2  <<<BB * 1024 / 256, 256>>>(c2w, c2bv, bn2g, bn2b, bn2m, bn2v);
    k_fc1   <<<BB * 64 / 256, 256>>>(fcW, fcb);
    k_head  <<<BB, 128>>>(fusW, fusb, cls1W, cls1b, cls3W, cls3b, out);
}